// round 2
// baseline (speedup 1.0000x reference)
#include <cuda_runtime.h>
#include <math.h>

#define NQ 8
#define TOK_PER_BLOCK 32
#define THREADS 256          // 256 threads * 4 cols = 1024 output columns
#define COLS_PER_THREAD 4

__global__ __launch_bounds__(THREADS)
void mhaq_kernel(const float* __restrict__ x,
                 const float* __restrict__ theta,
                 const float* __restrict__ W,      // [1024, 8] row-major
                 float* __restrict__ out,
                 int n_tokens)
{
    __shared__ float s_proj[TOK_PER_BLOCK][NQ];

    const int t = threadIdx.x;
    const int tokBase = blockIdx.x * TOK_PER_BLOCK;

    // ---- Phase 1: proj[tok][q] = cos(x[tok*1024 + q] + theta[q]) ----
    // 256 threads -> 32 tokens * 8 qubits, one value each.
    {
        const int tok = t >> 3;
        const int q   = t & 7;
        const int gtok = tokBase + tok;
        float v = 0.0f;
        if (gtok < n_tokens) {
            v = x[(size_t)gtok * 1024 + q] + theta[q];
        }
        s_proj[tok][q] = cosf(v);
    }

    // ---- Phase 2: load this thread's 4 rows of W (32 contiguous floats) ----
    float w[COLS_PER_THREAD][NQ];
    {
        const float4* Wv = reinterpret_cast<const float4*>(W + (size_t)t * 32);
        #pragma unroll
        for (int c = 0; c < COLS_PER_THREAD; ++c) {
            float4 a = Wv[c * 2 + 0];
            float4 b = Wv[c * 2 + 1];
            w[c][0] = a.x; w[c][1] = a.y; w[c][2] = a.z; w[c][3] = a.w;
            w[c][4] = b.x; w[c][5] = b.y; w[c][6] = b.z; w[c][7] = b.w;
        }
    }

    __syncthreads();

    // ---- Phase 3: for each token, 32 FMA -> one float4 store ----
    #pragma unroll 8
    for (int tok = 0; tok < TOK_PER_BLOCK; ++tok) {
        const int gtok = tokBase + tok;
        if (gtok >= n_tokens) break;

        float p[NQ];
        #pragma unroll
        for (int q = 0; q < NQ; ++q) p[q] = s_proj[tok][q];   // broadcast LDS

        float4 o;
        float acc0 = 0.f, acc1 = 0.f, acc2 = 0.f, acc3 = 0.f;
        #pragma unroll
        for (int q = 0; q < NQ; ++q) {
            acc0 = fmaf(p[q], w[0][q], acc0);
            acc1 = fmaf(p[q], w[1][q], acc1);
            acc2 = fmaf(p[q], w[2][q], acc2);
            acc3 = fmaf(p[q], w[3][q], acc3);
        }
        o.x = acc0; o.y = acc1; o.z = acc2; o.w = acc3;

        reinterpret_cast<float4*>(out + (size_t)gtok * 1024)[t] = o;
    }
}

extern "C" void kernel_launch(void* const* d_in, const int* in_sizes, int n_in,
                              void* d_out, int out_size) {
    const float* x     = (const float*)d_in[0];   // [4,4096,1024] f32
    const float* theta = (const float*)d_in[1];   // [8] f32
    const float* W     = (const float*)d_in[2];   // [1024,8] f32
    float* out = (float*)d_out;

    const int n_tokens = in_sizes[0] / 1024;      // 16384
    const int blocks = (n_tokens + TOK_PER_BLOCK - 1) / TOK_PER_BLOCK;

    mhaq_kernel<<<blocks, THREADS>>>(x, theta, W, out, n_tokens);
}